// round 11
// baseline (speedup 1.0000x reference)
#include <cuda_runtime.h>
#include <cuda_fp16.h>
#include <math.h>

// ---------------------------------------------------------------------------
// SpatialTransformerInputHead  (B=128, H=W=256, C=1)
//   conv1 5x5 1->14 + relu + maxpool2  (fp32 f32x2)         -> g_buf1 fp16 NHWC16
//   conv2 5x5 14->32 + relu + maxpool2 (fp16 HMMA, fp32 acc)-> g_buf2 fp32 NHWC
//   dense 119072->120 relu, 120->84 relu, 84->6 -> theta
//   bilinear grid sample + 1x1 conv + sigmoid -> [128,256,256,1]
// ---------------------------------------------------------------------------

typedef unsigned long long ull;
typedef unsigned int uint32;

#define BATCH 128
#define HW    256
#define P1    126
#define P2    61
#define FLAT  (61*61*32)   // 119072
#define KSPLITS 256
#define KCHUNK  466        // ceil(119072/256)

// --------- scratch -----------------------------------------------------------
__device__ __half g_buf1[(size_t)BATCH*P1*P1*16];  // conv1 pooled, NHWC16, fp16
__device__ __half g_w16[25*32*24];                 // conv2 weights fp16 [tap][co][k24]
__device__ float  g_buf2[(size_t)BATCH*FLAT];      // conv2 pooled, NHWC flat, fp32
__device__ float  g_part[(size_t)KSPLITS*BATCH*120];
__device__ float  g_theta[BATCH*6];

// --------- helpers -----------------------------------------------------------
__device__ __forceinline__ ull pk2(float v) {
    ull r;
    asm("mov.b64 %0, {%1, %2};" : "=l"(r) : "f"(v), "f"(v));
    return r;
}
__device__ __forceinline__ void upk2(ull v, float& lo, float& hi) {
    asm("mov.b64 {%0, %1}, %2;" : "=f"(lo), "=f"(hi) : "l"(v));
}
#define FMA2(d, a, b) asm("fma.rn.f32x2 %0, %1, %2, %0;" : "+l"(d) : "l"(a), "l"(b))

__device__ __forceinline__ uint32 smem_u32(const void* p) {
    uint32 a;
    asm("{ .reg .u64 t; cvta.to.shared.u64 t, %1; cvt.u32.u64 %0, t; }"
        : "=r"(a) : "l"(p));
    return a;
}

#define MMA_F16(c, a0, a1, a2, a3, b0, b1)                                     \
    asm volatile(                                                              \
        "mma.sync.aligned.m16n8k16.row.col.f32.f16.f16.f32 "                   \
        "{%0,%1,%2,%3}, {%4,%5,%6,%7}, {%8,%9}, {%0,%1,%2,%3};"                \
        : "+f"((c)[0]), "+f"((c)[1]), "+f"((c)[2]), "+f"((c)[3])               \
        : "r"(a0), "r"(a1), "r"(a2), "r"(a3), "r"(b0), "r"(b1))

#define LDSM_X4(r0, r1, r2, r3, addr)                                          \
    asm volatile("ldmatrix.sync.aligned.m8n8.x4.shared.b16 {%0,%1,%2,%3}, [%4];" \
        : "=r"(r0), "=r"(r1), "=r"(r2), "=r"(r3) : "r"(addr))

// ===========================================================================
// wprep: conv2 weights HWIO fp32 -> fp16 [tap][co(32)][ci pad 24], once.
// grid 25 (one tap per block), 256 threads.
// ===========================================================================
__global__ void __launch_bounds__(256) wprep_kernel(const float* __restrict__ w)
{
    const int tap = blockIdx.x;
    for (int i = threadIdx.x; i < 768; i += 256) {
        int n = i / 24, k = i - n*24;
        float v = (k < 14) ? w[tap*448 + k*32 + n] : 0.f;
        g_w16[tap*768 + i] = __float2half_rn(v);
    }
}

// ===========================================================================
// conv1 (5x5, 1->14) + relu + maxpool2, fp32 f32x2 math, fp16 NHWC16 output.
// grid (8,8,128), 256 threads.
// ===========================================================================
__global__ void __launch_bounds__(256) conv1_kernel(
    const float* __restrict__ x, const float* __restrict__ w,
    const float* __restrict__ bias)
{
    __shared__ __align__(16) float sw[352];
    __shared__ __align__(16) float sb[16];
    __shared__ __align__(16) float sin_[36*36];

    const int b  = blockIdx.z;
    const int ox = blockIdx.x * 32;
    const int oy = blockIdx.y * 32;
    const int tid = threadIdx.x;

    for (int i = tid; i < 350; i += 256) sw[i] = w[i];
    if (tid < 14)  sb[tid] = bias[tid];

    const float* xb = x + (size_t)b * (HW*HW);
    for (int i = tid; i < 36*36; i += 256) {
        int r = i / 36, c = i % 36;
        int gy = oy + r, gx = ox + c;
        sin_[i] = (gy < HW && gx < HW) ? xb[gy*HW + gx] : 0.f;
    }
    __syncthreads();

    const int tx = tid & 15, ty = tid >> 4;

    ull acc[4][7];
#pragma unroll
    for (int p = 0; p < 4; ++p)
#pragma unroll
        for (int j = 0; j < 7; ++j) acc[p][j] = 0ull;

    const float* ib = sin_ + (2*ty)*36 + 2*tx;
#pragma unroll
    for (int dy = 0; dy < 5; ++dy) {
        const float* ra = ib + dy*36;
        const float* rb = ra + 36;
#pragma unroll
        for (int dx = 0; dx < 5; ++dx) {
            ull p00 = pk2(ra[dx]);
            ull p01 = pk2(ra[dx+1]);
            ull p10 = pk2(rb[dx]);
            ull p11 = pk2(rb[dx+1]);
            const ull* wp = (const ull*)&sw[(dy*5 + dx)*14];
#pragma unroll
            for (int j = 0; j < 7; ++j) {
                ull wv = wp[j];
                FMA2(acc[0][j], p00, wv);
                FMA2(acc[1][j], p01, wv);
                FMA2(acc[2][j], p10, wv);
                FMA2(acc[3][j], p11, wv);
            }
        }
    }

    const int x0 = blockIdx.x*16 + tx;
    const int y0 = blockIdx.y*16 + ty;
    if (x0 < P1 && y0 < P1) {
        union { uint4 u[2]; __half2 h2[8]; } pk;
#pragma unroll
        for (int j = 0; j < 7; ++j) {
            float l0,h0,l1,h1,l2,h2,l3,h3;
            upk2(acc[0][j], l0, h0);
            upk2(acc[1][j], l1, h1);
            upk2(acc[2][j], l2, h2);
            upk2(acc[3][j], l3, h3);
            float m0 = fmaxf(fmaxf(l0,l1), fmaxf(l2,l3)) + sb[2*j];
            float m1 = fmaxf(fmaxf(h0,h1), fmaxf(h2,h3)) + sb[2*j+1];
            pk.h2[j] = __float22half2_rn(make_float2(fmaxf(m0, 0.f), fmaxf(m1, 0.f)));
        }
        pk.h2[7] = __float22half2_rn(make_float2(0.f, 0.f));
        uint4* dst = (uint4*)(g_buf1 + ((size_t)(b*P1 + y0)*P1 + x0)*16);
        dst[0] = pk.u[0];
        dst[1] = pk.u[1];
    }
}

// ===========================================================================
// conv2 via fp16 mma.sync m16n8k16 (fp32 accum): 5x5 conv = 25 shifted GEMMs.
// Block: 8x16 pooled = 16x32 conv positions, 256 threads (8 warps),
// each warp 2 conv rows x 32 cols (M=64) x N=32.  2 blocks/SM.
// A: [20*36 pos][24 pad fp16] (48B rows, conflict-free LDSM).
// W: fp16 [25 tap][32 co][24 k] copied from g_w16; B-frags via ldmatrix.
// Epilogue: 2x2 maxpool + bias + relu -> fp32 NHWC flat g_buf2.
// ===========================================================================
#define C2_A_B    (720*48)                  // 34560 B (20 rows x 36 cols)
#define C2_W_B    (25*32*48)                // 38400 B
#define C2_SMEM_B (C2_A_B + C2_W_B + 128)   // 73088 B

__global__ void __launch_bounds__(256, 2) conv2_kernel(const float* __restrict__ bias)
{
    extern __shared__ __align__(16) unsigned char smem[];
    __half* At = (__half*)smem;                        // [pos 20x36][24]
    __half* Wt = (__half*)(smem + C2_A_B);             // [tap][co32][24]
    float*  sb = (float*)(smem + C2_A_B + C2_W_B);     // [32]

    const int b   = blockIdx.z;
    const int px0 = blockIdx.x * 16;
    const int py0 = blockIdx.y * 8;
    const int ix0 = px0 * 2;
    const int iy0 = py0 * 2;
    const int tid = threadIdx.x;

    // W: straight 38.4KB vector copy from preconverted fp16
    {
        const uint4* ws = (const uint4*)g_w16;
        uint4* wd = (uint4*)Wt;
        for (int i = tid; i < C2_W_B/16; i += 256) wd[i] = ws[i];
    }
    if (tid < 32) sb[tid] = bias[tid];

    // A tile: 20x36 positions, 32B fp16 copy + 16B zero pad (48B rows)
    for (int p = tid; p < 720; p += 256) {
        int r = p / 36, c = p - r*36;
        int gy = iy0 + r, gx = ix0 + c;
        uint4 u0 = make_uint4(0,0,0,0), u1 = u0;
        if (gy < P1 && gx < P1) {
            const uint4* s4 = (const uint4*)(g_buf1 + ((size_t)(b*P1 + gy)*P1 + gx)*16);
            u0 = s4[0]; u1 = s4[1];
        }
        uint4* d = (uint4*)(At + p*24);
        d[0] = u0; d[1] = u1; d[2] = make_uint4(0,0,0,0);
    }
    __syncthreads();

    const int warp = tid >> 5, lane = tid & 31;
    const int y0 = 2 * warp;                 // conv rows y0, y0+1 (0..15)
    const uint32 atb = smem_u32(At);
    const uint32 wtb = smem_u32(Wt);

    // A-LDSM per-lane offset: 16 x-position rows (48B stride), 16B k-halves
    const uint32 aoff = (uint32)((lane & 15)*48 + (lane >> 4)*16);
    // B-LDSM per-lane offset: mat0..3 = (n0-7,k0-7),(n0-7,k8-15),(n8-15,k0-7),(n8-15,k8-15)
    const uint32 boff = (uint32)(((lane & 7) + ((lane >> 4) & 1)*8)*48
                                 + ((lane >> 3) & 1)*16);

    float cacc[2][2][4][4];
#pragma unroll
    for (int s = 0; s < 2; ++s)
#pragma unroll
        for (int xh = 0; xh < 2; ++xh)
#pragma unroll
            for (int nf = 0; nf < 4; ++nf)
#pragma unroll
                for (int k = 0; k < 4; ++k) cacc[s][xh][nf][k] = 0.f;

#pragma unroll 1
    for (int tap = 0; tap < 25; ++tap) {
        const int dy = tap / 5, dx = tap - 5*dy;

        // B fragments for all 4 n-frags: 2x ldmatrix.x4
        const uint32 wb = wtb + (uint32)(tap*1536) + boff;
        uint32 b00, b01, b10, b11, b20, b21, b30, b31;
        LDSM_X4(b00, b01, b10, b11, wb);            // nf0: b0,b1 ; nf1: b0,b1
        LDSM_X4(b20, b21, b30, b31, wb + 768);      // nf2, nf3 (n offset 16 rows)

#pragma unroll
        for (int s = 0; s < 2; ++s) {
            const int rowbase = (y0 + s + dy)*36 + dx;
#pragma unroll
            for (int xh = 0; xh < 2; ++xh) {
                uint32 a0, a1, a2, a3;
                LDSM_X4(a0, a1, a2, a3,
                        atb + (uint32)((rowbase + xh*16)*48) + aoff);
                MMA_F16(cacc[s][xh][0], a0, a1, a2, a3, b00, b01);
                MMA_F16(cacc[s][xh][1], a0, a1, a2, a3, b10, b11);
                MMA_F16(cacc[s][xh][2], a0, a1, a2, a3, b20, b21);
                MMA_F16(cacc[s][xh][3], a0, a1, a2, a3, b30, b31);
            }
        }
    }

    // epilogue: 2x2 maxpool (y across s, x across frag-row pairs) + bias + relu
    const int py = py0 + warp;
    const int r  = lane >> 2;
    const bool active = ((r & 1) == 0);
    const int j = r >> 1;
    const int n0 = (lane & 3) * 2;

#pragma unroll
    for (int xh = 0; xh < 2; ++xh)
#pragma unroll
    for (int nf = 0; nf < 4; ++nf) {
        float m0 = fmaxf(cacc[0][xh][nf][0], cacc[1][xh][nf][0]);
        float m1 = fmaxf(cacc[0][xh][nf][1], cacc[1][xh][nf][1]);
        float m2 = fmaxf(cacc[0][xh][nf][2], cacc[1][xh][nf][2]);
        float m3 = fmaxf(cacc[0][xh][nf][3], cacc[1][xh][nf][3]);
        float o0 = fmaxf(m0, __shfl_down_sync(0xffffffffu, m0, 4));
        float o1 = fmaxf(m1, __shfl_down_sync(0xffffffffu, m1, 4));
        float o2 = fmaxf(m2, __shfl_down_sync(0xffffffffu, m2, 4));
        float o3 = fmaxf(m3, __shfl_down_sync(0xffffffffu, m3, 4));
        if (active && py < P2) {
            const int ch  = nf*8 + n0;
            const float b0v = sb[ch], b1v = sb[ch+1];
            const int pxa = px0 + xh*8 + j;
            const int pxb = pxa + 4;
            if (pxa < P2) {
                float2 v = make_float2(fmaxf(o0 + b0v, 0.f), fmaxf(o1 + b1v, 0.f));
                *(float2*)(g_buf2 + (((size_t)b*P2 + py)*P2 + pxa)*32 + ch) = v;
            }
            if (pxb < P2) {
                float2 v = make_float2(fmaxf(o2 + b0v, 0.f), fmaxf(o3 + b1v, 0.f));
                *(float2*)(g_buf2 + (((size_t)b*P2 + py)*P2 + pxb)*32 + ch) = v;
            }
        }
    }
}

// ===========================================================================
// dense1 split-K GEMM: [128 x 119072] @ [119072 x 120] -> partials.
// grid KSPLITS(=256) blocks, 512 threads; f32x2-packed inner loop.
// ===========================================================================
__global__ void __launch_bounds__(512) dense1_kernel(const float* __restrict__ w)
{
    __shared__ __align__(16) float As[32*129];
    __shared__ __align__(16) float Ws[32*120];

    const int k0   = blockIdx.x * KCHUNK;
    const int kend = min(k0 + KCHUNK, FLAT);
    const int tid  = threadIdx.x;
    const int bb   = tid & 127;
    const int g    = tid >> 7;          // 0..3 -> 30 output cols each

    ull acc[15];
#pragma unroll
    for (int j = 0; j < 15; ++j) acc[j] = 0ull;

    for (int kb = k0; kb < kend; kb += 32) {
        for (int i = tid; i < 128*32; i += 512) {
            int r  = i >> 5;
            int kk = i & 31;
            int k  = kb + kk;
            As[kk*129 + r] = (k < kend) ? g_buf2[(size_t)r*FLAT + k] : 0.f;
        }
        for (int i = tid; i < 32*120; i += 512) {
            int kk = i / 120, oo = i - kk*120;
            int k = kb + kk;
            Ws[i] = (k < kend) ? w[(size_t)k*120 + oo] : 0.f;
        }
        __syncthreads();
#pragma unroll
        for (int kk = 0; kk < 32; ++kk) {
            ull a2 = pk2(As[kk*129 + bb]);
            const ull* wsp = (const ull*)&Ws[kk*120 + g*30];
#pragma unroll
            for (int j = 0; j < 15; ++j)
                FMA2(acc[j], a2, wsp[j]);
        }
        __syncthreads();
    }

    float* p = g_part + ((size_t)blockIdx.x*BATCH + bb)*120 + g*30;
#pragma unroll
    for (int j = 0; j < 15; ++j) {
        float lo, hi;
        upk2(acc[j], lo, hi);
        p[2*j]   = lo;
        p[2*j+1] = hi;
    }
}

// ===========================================================================
// dense23: reduce split-K partials (4-way ILP) + bias + relu -> h1;
//          h2 = relu(h1 @ d2_w + b2);  theta = h2 @ d3_w + b3.
// ===========================================================================
__global__ void __launch_bounds__(128) dense23_kernel(
    const float* __restrict__ d1b,
    const float* __restrict__ d2w, const float* __restrict__ d2b,
    const float* __restrict__ d3w, const float* __restrict__ d3b)
{
    __shared__ float h1[120];
    __shared__ float h2[84];
    const int b = blockIdx.x, t = threadIdx.x;

    if (t < 120) {
        const float* gp = g_part + (size_t)b*120 + t;
        float s0 = d1b[t], s1 = 0.f, s2 = 0.f, s3 = 0.f;
#pragma unroll 4
        for (int i = 0; i < KSPLITS; i += 4) {
            s0 += gp[(size_t)(i+0)*BATCH*120];
            s1 += gp[(size_t)(i+1)*BATCH*120];
            s2 += gp[(size_t)(i+2)*BATCH*120];
            s3 += gp[(size_t)(i+3)*BATCH*120];
        }
        h1[t] = fmaxf((s0 + s1) + (s2 + s3), 0.f);
    }
    __syncthreads();
    if (t < 84) {
        float s = d2b[t];
#pragma unroll 4
        for (int k = 0; k < 120; ++k)
            s = fmaf(h1[k], d2w[k*84 + t], s);
        h2[t] = fmaxf(s, 0.f);
    }
    __syncthreads();
    if (t < 6) {
        float s = d3b[t];
#pragma unroll 4
        for (int k = 0; k < 84; ++k)
            s = fmaf(h2[k], d3w[k*6 + t], s);
        g_theta[b*6 + t] = s;
    }
}

// ===========================================================================
// sampler: affine grid + bilinear sample + 1x1 conv + sigmoid.
// ===========================================================================
__global__ void __launch_bounds__(256) sampler_kernel(
    const float* __restrict__ x, const float* __restrict__ ow,
    const float* __restrict__ ob, float* __restrict__ out)
{
    __shared__ float th[6];
    const int b = blockIdx.y;
    const int h = blockIdx.x;
    const int w = threadIdx.x;
    if (w < 6) th[w] = g_theta[b*6 + w];
    __syncthreads();

    const float gx = (float)w * (2.f/256.f) - 1.f;
    const float gy = (float)h * (2.f/256.f) - 1.f;
    const float px = (th[0]*gx + th[1]*gy + th[2] + 1.f) * 128.f;
    const float py = (th[3]*gx + th[4]*gy + th[5] + 1.f) * 128.f;

    const int fx = (int)floorf(px);
    const int fy = (int)floorf(py);
    const int x1 = min(max(fx,     0), HW-1);
    const int x2 = min(max(fx + 1, 0), HW-1);
    const int y1 = min(max(fy,     0), HW-1);
    const int y2 = min(max(fy + 1, 0), HW-1);

    const float* img = x + (size_t)b * (HW*HW);
    const float p11 = img[y1*HW + x1];
    const float p12 = img[y2*HW + x1];
    const float p21 = img[y1*HW + x2];
    const float p22 = img[y2*HW + x2];

    const float wx1 = (float)x2 - px;
    const float wx2 = px - (float)x1;
    const float wy1 = (float)y2 - py;
    const float wy2 = py - (float)y1;

    const float r = wx1*(wy1*p11 + wy2*p12) + wx2*(wy1*p21 + wy2*p22);
    const float t = r * __ldg(ow) + __ldg(ob);
    out[((size_t)b*HW + h)*HW + w] = 1.f / (1.f + expf(-t));
}

// ===========================================================================
// launch
// ===========================================================================
extern "C" void kernel_launch(void* const* d_in, const int* in_sizes, int n_in,
                              void* d_out, int out_size)
{
    const float* x      = (const float*)d_in[0];
    const float* c1w    = (const float*)d_in[1];
    const float* c1b    = (const float*)d_in[2];
    const float* c2w    = (const float*)d_in[3];
    const float* c2b    = (const float*)d_in[4];
    const float* d1w    = (const float*)d_in[5];
    const float* d1b    = (const float*)d_in[6];
    const float* d2w    = (const float*)d_in[7];
    const float* d2b    = (const float*)d_in[8];
    const float* d3w    = (const float*)d_in[9];
    const float* d3b    = (const float*)d_in[10];
    const float* outw   = (const float*)d_in[11];
    const float* outb   = (const float*)d_in[12];
    float* out = (float*)d_out;

    (void)in_sizes; (void)n_in; (void)out_size;

    cudaFuncSetAttribute(conv2_kernel,
                         cudaFuncAttributeMaxDynamicSharedMemorySize, C2_SMEM_B);

    wprep_kernel<<<25, 256>>>(c2w);
    conv1_kernel<<<dim3(8, 8, BATCH), 256>>>(x, c1w, c1b);
    conv2_kernel<<<dim3(4, 8, BATCH), 256, C2_SMEM_B>>>(c2b);
    dense1_kernel<<<KSPLITS, 512>>>(d1w);
    dense23_kernel<<<BATCH, 128>>>(d1b, d2w, d2b, d3w, d3b);
    sampler_kernel<<<dim3(HW, BATCH), 256>>>(x, outw, outb, out);
}

// round 12
// speedup vs baseline: 1.0057x; 1.0057x over previous
#include <cuda_runtime.h>
#include <cuda_fp16.h>
#include <math.h>

// ---------------------------------------------------------------------------
// SpatialTransformerInputHead  (B=128, H=W=256, C=1)
//   conv1 5x5 1->14 + relu + maxpool2  (fp32 f32x2)         -> g_buf1 fp16 NHWC16
//   conv2 5x5 14->32 + relu + maxpool2 (fp16 HMMA, fp32 acc)-> g_buf2 fp32 NHWC
//   dense 119072->120 relu, 120->84 relu, 84->6 -> theta
//   bilinear grid sample + 1x1 conv + sigmoid -> [128,256,256,1]
// ---------------------------------------------------------------------------

typedef unsigned long long ull;
typedef unsigned int uint32;

#define BATCH 128
#define HW    256
#define P1    126
#define P2    61
#define FLAT  (61*61*32)   // 119072
#define KSPLITS 256
#define KCHUNK  466        // ceil(119072/256)

// --------- scratch -----------------------------------------------------------
__device__ __half g_buf1[(size_t)BATCH*P1*P1*16];  // conv1 pooled, NHWC16, fp16
__device__ __half g_w16[25*32*24];                 // conv2 weights fp16 [tap][co][k24]
__device__ float  g_buf2[(size_t)BATCH*FLAT];      // conv2 pooled, NHWC flat, fp32
__device__ float  g_part[(size_t)KSPLITS*BATCH*120];
__device__ float  g_theta[BATCH*6];

// --------- helpers -----------------------------------------------------------
__device__ __forceinline__ ull pk2(float v) {
    ull r;
    asm("mov.b64 %0, {%1, %2};" : "=l"(r) : "f"(v), "f"(v));
    return r;
}
__device__ __forceinline__ void upk2(ull v, float& lo, float& hi) {
    asm("mov.b64 {%0, %1}, %2;" : "=f"(lo), "=f"(hi) : "l"(v));
}
#define FMA2(d, a, b) asm("fma.rn.f32x2 %0, %1, %2, %0;" : "+l"(d) : "l"(a), "l"(b))

__device__ __forceinline__ uint32 smem_u32(const void* p) {
    uint32 a;
    asm("{ .reg .u64 t; cvta.to.shared.u64 t, %1; cvt.u32.u64 %0, t; }"
        : "=r"(a) : "l"(p));
    return a;
}

#define MMA_F16(c, a0, a1, a2, a3, b0, b1)                                     \
    asm volatile(                                                              \
        "mma.sync.aligned.m16n8k16.row.col.f32.f16.f16.f32 "                   \
        "{%0,%1,%2,%3}, {%4,%5,%6,%7}, {%8,%9}, {%0,%1,%2,%3};"                \
        : "+f"((c)[0]), "+f"((c)[1]), "+f"((c)[2]), "+f"((c)[3])               \
        : "r"(a0), "r"(a1), "r"(a2), "r"(a3), "r"(b0), "r"(b1))

#define LDSM_X4(r0, r1, r2, r3, addr)                                          \
    asm volatile("ldmatrix.sync.aligned.m8n8.x4.shared.b16 {%0,%1,%2,%3}, [%4];" \
        : "=r"(r0), "=r"(r1), "=r"(r2), "=r"(r3) : "r"(addr))

// ===========================================================================
// wprep: conv2 weights HWIO fp32 -> fp16 [tap][co(32)][ci pad 24], once.
// grid 25 (one tap per block), 256 threads.
// ===========================================================================
__global__ void __launch_bounds__(256) wprep_kernel(const float* __restrict__ w)
{
    const int tap = blockIdx.x;
    for (int i = threadIdx.x; i < 768; i += 256) {
        int n = i / 24, k = i - n*24;
        float v = (k < 14) ? w[tap*448 + k*32 + n] : 0.f;
        g_w16[tap*768 + i] = __float2half_rn(v);
    }
}

// ===========================================================================
// conv1 (5x5, 1->14) + relu + maxpool2, fp32 f32x2 math, fp16 NHWC16 output.
// grid (8,8,128), 256 threads.
// ===========================================================================
__global__ void __launch_bounds__(256) conv1_kernel(
    const float* __restrict__ x, const float* __restrict__ w,
    const float* __restrict__ bias)
{
    __shared__ __align__(16) float sw[352];
    __shared__ __align__(16) float sb[16];
    __shared__ __align__(16) float sin_[36*36];

    const int b  = blockIdx.z;
    const int ox = blockIdx.x * 32;
    const int oy = blockIdx.y * 32;
    const int tid = threadIdx.x;

    for (int i = tid; i < 350; i += 256) sw[i] = w[i];
    if (tid < 14)  sb[tid] = bias[tid];

    const float* xb = x + (size_t)b * (HW*HW);
    for (int i = tid; i < 36*36; i += 256) {
        int r = i / 36, c = i % 36;
        int gy = oy + r, gx = ox + c;
        sin_[i] = (gy < HW && gx < HW) ? xb[gy*HW + gx] : 0.f;
    }
    __syncthreads();

    const int tx = tid & 15, ty = tid >> 4;

    ull acc[4][7];
#pragma unroll
    for (int p = 0; p < 4; ++p)
#pragma unroll
        for (int j = 0; j < 7; ++j) acc[p][j] = 0ull;

    const float* ib = sin_ + (2*ty)*36 + 2*tx;
#pragma unroll
    for (int dy = 0; dy < 5; ++dy) {
        const float* ra = ib + dy*36;
        const float* rb = ra + 36;
#pragma unroll
        for (int dx = 0; dx < 5; ++dx) {
            ull p00 = pk2(ra[dx]);
            ull p01 = pk2(ra[dx+1]);
            ull p10 = pk2(rb[dx]);
            ull p11 = pk2(rb[dx+1]);
            const ull* wp = (const ull*)&sw[(dy*5 + dx)*14];
#pragma unroll
            for (int j = 0; j < 7; ++j) {
                ull wv = wp[j];
                FMA2(acc[0][j], p00, wv);
                FMA2(acc[1][j], p01, wv);
                FMA2(acc[2][j], p10, wv);
                FMA2(acc[3][j], p11, wv);
            }
        }
    }

    const int x0 = blockIdx.x*16 + tx;
    const int y0 = blockIdx.y*16 + ty;
    if (x0 < P1 && y0 < P1) {
        union { uint4 u[2]; __half2 h2[8]; } pk;
#pragma unroll
        for (int j = 0; j < 7; ++j) {
            float l0,h0,l1,h1,l2,h2,l3,h3;
            upk2(acc[0][j], l0, h0);
            upk2(acc[1][j], l1, h1);
            upk2(acc[2][j], l2, h2);
            upk2(acc[3][j], l3, h3);
            float m0 = fmaxf(fmaxf(l0,l1), fmaxf(l2,l3)) + sb[2*j];
            float m1 = fmaxf(fmaxf(h0,h1), fmaxf(h2,h3)) + sb[2*j+1];
            pk.h2[j] = __float22half2_rn(make_float2(fmaxf(m0, 0.f), fmaxf(m1, 0.f)));
        }
        pk.h2[7] = __float22half2_rn(make_float2(0.f, 0.f));
        uint4* dst = (uint4*)(g_buf1 + ((size_t)(b*P1 + y0)*P1 + x0)*16);
        dst[0] = pk.u[0];
        dst[1] = pk.u[1];
    }
}

// ===========================================================================
// conv2 via fp16 mma.sync m16n8k16 (fp32 accum): 5x5 conv = 25 shifted GEMMs.
// Block: 8x16 pooled = 16x32 conv positions, 256 threads (8 warps),
// each warp 2 conv rows x 32 cols (M=64) x N=32.  2 blocks/SM.
// A: [20*36 pos][24 pad fp16] (48B rows, conflict-free LDSM).
// W: fp16 [25 tap][32 co][24 k] copied from g_w16; B-frags via ldmatrix.
// Epilogue: 2x2 maxpool + bias + relu -> fp32 NHWC flat g_buf2.
// ===========================================================================
#define C2_A_B    (720*48)                  // 34560 B (20 rows x 36 cols)
#define C2_W_B    (25*32*48)                // 38400 B
#define C2_SMEM_B (C2_A_B + C2_W_B + 128)   // 73088 B

__global__ void __launch_bounds__(256, 2) conv2_kernel(const float* __restrict__ bias)
{
    extern __shared__ __align__(16) unsigned char smem[];
    __half* At = (__half*)smem;                        // [pos 20x36][24]
    __half* Wt = (__half*)(smem + C2_A_B);             // [tap][co32][24]
    float*  sb = (float*)(smem + C2_A_B + C2_W_B);     // [32]

    const int b   = blockIdx.z;
    const int px0 = blockIdx.x * 16;
    const int py0 = blockIdx.y * 8;
    const int ix0 = px0 * 2;
    const int iy0 = py0 * 2;
    const int tid = threadIdx.x;

    // W: straight 38.4KB vector copy from preconverted fp16
    {
        const uint4* ws = (const uint4*)g_w16;
        uint4* wd = (uint4*)Wt;
        for (int i = tid; i < C2_W_B/16; i += 256) wd[i] = ws[i];
    }
    if (tid < 32) sb[tid] = bias[tid];

    // A tile: 20x36 positions, 32B fp16 copy + 16B zero pad (48B rows)
    for (int p = tid; p < 720; p += 256) {
        int r = p / 36, c = p - r*36;
        int gy = iy0 + r, gx = ix0 + c;
        uint4 u0 = make_uint4(0,0,0,0), u1 = u0;
        if (gy < P1 && gx < P1) {
            const uint4* s4 = (const uint4*)(g_buf1 + ((size_t)(b*P1 + gy)*P1 + gx)*16);
            u0 = s4[0]; u1 = s4[1];
        }
        uint4* d = (uint4*)(At + p*24);
        d[0] = u0; d[1] = u1; d[2] = make_uint4(0,0,0,0);
    }
    __syncthreads();

    const int warp = tid >> 5, lane = tid & 31;
    const int y0 = 2 * warp;                 // conv rows y0, y0+1 (0..15)
    const uint32 atb = smem_u32(At);
    const uint32 wtb = smem_u32(Wt);

    // A-LDSM per-lane offset: 16 x-position rows (48B stride), 16B k-halves
    const uint32 aoff = (uint32)((lane & 15)*48 + (lane >> 4)*16);
    // B-LDSM per-lane offset: mat0..3 = (n0-7,k0-7),(n0-7,k8-15),(n8-15,k0-7),(n8-15,k8-15)
    const uint32 boff = (uint32)(((lane & 7) + ((lane >> 4) & 1)*8)*48
                                 + ((lane >> 3) & 1)*16);

    float cacc[2][2][4][4];
#pragma unroll
    for (int s = 0; s < 2; ++s)
#pragma unroll
        for (int xh = 0; xh < 2; ++xh)
#pragma unroll
            for (int nf = 0; nf < 4; ++nf)
#pragma unroll
                for (int k = 0; k < 4; ++k) cacc[s][xh][nf][k] = 0.f;

#pragma unroll 1
    for (int tap = 0; tap < 25; ++tap) {
        const int dy = tap / 5, dx = tap - 5*dy;

        // B fragments for all 4 n-frags: 2x ldmatrix.x4
        const uint32 wb = wtb + (uint32)(tap*1536) + boff;
        uint32 b00, b01, b10, b11, b20, b21, b30, b31;
        LDSM_X4(b00, b01, b10, b11, wb);            // nf0: b0,b1 ; nf1: b0,b1
        LDSM_X4(b20, b21, b30, b31, wb + 768);      // nf2, nf3 (n offset 16 rows)

#pragma unroll
        for (int s = 0; s < 2; ++s) {
            const int rowbase = (y0 + s + dy)*36 + dx;
#pragma unroll
            for (int xh = 0; xh < 2; ++xh) {
                uint32 a0, a1, a2, a3;
                LDSM_X4(a0, a1, a2, a3,
                        atb + (uint32)((rowbase + xh*16)*48) + aoff);
                MMA_F16(cacc[s][xh][0], a0, a1, a2, a3, b00, b01);
                MMA_F16(cacc[s][xh][1], a0, a1, a2, a3, b10, b11);
                MMA_F16(cacc[s][xh][2], a0, a1, a2, a3, b20, b21);
                MMA_F16(cacc[s][xh][3], a0, a1, a2, a3, b30, b31);
            }
        }
    }

    // epilogue: 2x2 maxpool (y across s, x across frag-row pairs) + bias + relu
    const int py = py0 + warp;
    const int r  = lane >> 2;
    const bool active = ((r & 1) == 0);
    const int j = r >> 1;
    const int n0 = (lane & 3) * 2;

#pragma unroll
    for (int xh = 0; xh < 2; ++xh)
#pragma unroll
    for (int nf = 0; nf < 4; ++nf) {
        float m0 = fmaxf(cacc[0][xh][nf][0], cacc[1][xh][nf][0]);
        float m1 = fmaxf(cacc[0][xh][nf][1], cacc[1][xh][nf][1]);
        float m2 = fmaxf(cacc[0][xh][nf][2], cacc[1][xh][nf][2]);
        float m3 = fmaxf(cacc[0][xh][nf][3], cacc[1][xh][nf][3]);
        float o0 = fmaxf(m0, __shfl_down_sync(0xffffffffu, m0, 4));
        float o1 = fmaxf(m1, __shfl_down_sync(0xffffffffu, m1, 4));
        float o2 = fmaxf(m2, __shfl_down_sync(0xffffffffu, m2, 4));
        float o3 = fmaxf(m3, __shfl_down_sync(0xffffffffu, m3, 4));
        if (active && py < P2) {
            const int ch  = nf*8 + n0;
            const float b0v = sb[ch], b1v = sb[ch+1];
            const int pxa = px0 + xh*8 + j;
            const int pxb = pxa + 4;
            if (pxa < P2) {
                float2 v = make_float2(fmaxf(o0 + b0v, 0.f), fmaxf(o1 + b1v, 0.f));
                *(float2*)(g_buf2 + (((size_t)b*P2 + py)*P2 + pxa)*32 + ch) = v;
            }
            if (pxb < P2) {
                float2 v = make_float2(fmaxf(o2 + b0v, 0.f), fmaxf(o3 + b1v, 0.f));
                *(float2*)(g_buf2 + (((size_t)b*P2 + py)*P2 + pxb)*32 + ch) = v;
            }
        }
    }
}

// ===========================================================================
// dense1 split-K GEMM: [128 x 119072] @ [119072 x 120] -> partials.
// grid KSPLITS(=256) blocks, 512 threads; f32x2-packed inner loop.
// ===========================================================================
__global__ void __launch_bounds__(512) dense1_kernel(const float* __restrict__ w)
{
    __shared__ __align__(16) float As[32*129];
    __shared__ __align__(16) float Ws[32*120];

    const int k0   = blockIdx.x * KCHUNK;
    const int kend = min(k0 + KCHUNK, FLAT);
    const int tid  = threadIdx.x;
    const int bb   = tid & 127;
    const int g    = tid >> 7;          // 0..3 -> 30 output cols each

    ull acc[15];
#pragma unroll
    for (int j = 0; j < 15; ++j) acc[j] = 0ull;

    for (int kb = k0; kb < kend; kb += 32) {
        for (int i = tid; i < 128*32; i += 512) {
            int r  = i >> 5;
            int kk = i & 31;
            int k  = kb + kk;
            As[kk*129 + r] = (k < kend) ? g_buf2[(size_t)r*FLAT + k] : 0.f;
        }
        for (int i = tid; i < 32*120; i += 512) {
            int kk = i / 120, oo = i - kk*120;
            int k = kb + kk;
            Ws[i] = (k < kend) ? w[(size_t)k*120 + oo] : 0.f;
        }
        __syncthreads();
#pragma unroll
        for (int kk = 0; kk < 32; ++kk) {
            ull a2 = pk2(As[kk*129 + bb]);
            const ull* wsp = (const ull*)&Ws[kk*120 + g*30];
#pragma unroll
            for (int j = 0; j < 15; ++j)
                FMA2(acc[j], a2, wsp[j]);
        }
        __syncthreads();
    }

    float* p = g_part + ((size_t)blockIdx.x*BATCH + bb)*120 + g*30;
#pragma unroll
    for (int j = 0; j < 15; ++j) {
        float lo, hi;
        upk2(acc[j], lo, hi);
        p[2*j]   = lo;
        p[2*j+1] = hi;
    }
}

// ===========================================================================
// dense23: reduce split-K partials (4-way ILP) + bias + relu -> h1;
//          h2 = relu(h1 @ d2_w + b2);  theta = h2 @ d3_w + b3.
// ===========================================================================
__global__ void __launch_bounds__(128) dense23_kernel(
    const float* __restrict__ d1b,
    const float* __restrict__ d2w, const float* __restrict__ d2b,
    const float* __restrict__ d3w, const float* __restrict__ d3b)
{
    __shared__ float h1[120];
    __shared__ float h2[84];
    const int b = blockIdx.x, t = threadIdx.x;

    if (t < 120) {
        const float* gp = g_part + (size_t)b*120 + t;
        float s0 = d1b[t], s1 = 0.f, s2 = 0.f, s3 = 0.f;
#pragma unroll 4
        for (int i = 0; i < KSPLITS; i += 4) {
            s0 += gp[(size_t)(i+0)*BATCH*120];
            s1 += gp[(size_t)(i+1)*BATCH*120];
            s2 += gp[(size_t)(i+2)*BATCH*120];
            s3 += gp[(size_t)(i+3)*BATCH*120];
        }
        h1[t] = fmaxf((s0 + s1) + (s2 + s3), 0.f);
    }
    __syncthreads();
    if (t < 84) {
        float s = d2b[t];
#pragma unroll 4
        for (int k = 0; k < 120; ++k)
            s = fmaf(h1[k], d2w[k*84 + t], s);
        h2[t] = fmaxf(s, 0.f);
    }
    __syncthreads();
    if (t < 6) {
        float s = d3b[t];
#pragma unroll 4
        for (int k = 0; k < 84; ++k)
            s = fmaf(h2[k], d3w[k*6 + t], s);
        g_theta[b*6 + t] = s;
    }
}

// ===========================================================================
// sampler: affine grid + bilinear sample + 1x1 conv + sigmoid.
// ===========================================================================
__global__ void __launch_bounds__(256) sampler_kernel(
    const float* __restrict__ x, const float* __restrict__ ow,
    const float* __restrict__ ob, float* __restrict__ out)
{
    __shared__ float th[6];
    const int b = blockIdx.y;
    const int h = blockIdx.x;
    const int w = threadIdx.x;
    if (w < 6) th[w] = g_theta[b*6 + w];
    __syncthreads();

    const float gx = (float)w * (2.f/256.f) - 1.f;
    const float gy = (float)h * (2.f/256.f) - 1.f;
    const float px = (th[0]*gx + th[1]*gy + th[2] + 1.f) * 128.f;
    const float py = (th[3]*gx + th[4]*gy + th[5] + 1.f) * 128.f;

    const int fx = (int)floorf(px);
    const int fy = (int)floorf(py);
    const int x1 = min(max(fx,     0), HW-1);
    const int x2 = min(max(fx + 1, 0), HW-1);
    const int y1 = min(max(fy,     0), HW-1);
    const int y2 = min(max(fy + 1, 0), HW-1);

    const float* img = x + (size_t)b * (HW*HW);
    const float p11 = img[y1*HW + x1];
    const float p12 = img[y2*HW + x1];
    const float p21 = img[y1*HW + x2];
    const float p22 = img[y2*HW + x2];

    const float wx1 = (float)x2 - px;
    const float wx2 = px - (float)x1;
    const float wy1 = (float)y2 - py;
    const float wy2 = py - (float)y1;

    const float r = wx1*(wy1*p11 + wy2*p12) + wx2*(wy1*p21 + wy2*p22);
    const float t = r * __ldg(ow) + __ldg(ob);
    out[((size_t)b*HW + h)*HW + w] = 1.f / (1.f + expf(-t));
}

// ===========================================================================
// launch
// ===========================================================================
extern "C" void kernel_launch(void* const* d_in, const int* in_sizes, int n_in,
                              void* d_out, int out_size)
{
    const float* x      = (const float*)d_in[0];
    const float* c1w    = (const float*)d_in[1];
    const float* c1b    = (const float*)d_in[2];
    const float* c2w    = (const float*)d_in[3];
    const float* c2b    = (const float*)d_in[4];
    const float* d1w    = (const float*)d_in[5];
    const float* d1b    = (const float*)d_in[6];
    const float* d2w    = (const float*)d_in[7];
    const float* d2b    = (const float*)d_in[8];
    const float* d3w    = (const float*)d_in[9];
    const float* d3b    = (const float*)d_in[10];
    const float* outw   = (const float*)d_in[11];
    const float* outb   = (const float*)d_in[12];
    float* out = (float*)d_out;

    (void)in_sizes; (void)n_in; (void)out_size;

    cudaFuncSetAttribute(conv2_kernel,
                         cudaFuncAttributeMaxDynamicSharedMemorySize, C2_SMEM_B);

    wprep_kernel<<<25, 256>>>(c2w);
    conv1_kernel<<<dim3(8, 8, BATCH), 256>>>(x, c1w, c1b);
    conv2_kernel<<<dim3(4, 8, BATCH), 256, C2_SMEM_B>>>(c2b);
    dense1_kernel<<<KSPLITS, 512>>>(d1w);
    dense23_kernel<<<BATCH, 128>>>(d1b, d2w, d2b, d3w, d3b);
    sampler_kernel<<<dim3(HW, BATCH), 256>>>(x, outw, outb, out);
}